// round 1
// baseline (speedup 1.0000x reference)
#include <cuda_runtime.h>

// ---------------- problem constants (fixed shapes) ----------------
#define Nn   65536          // total nodes
#define Ee   2097152        // edges
#define HID  32
#define GNUM 8
#define ISZ  8192
#define OSZ  33
#define FEAT (Nn * HID)

// ---------------- static device scratch ----------------
__device__ __align__(128) float g_dinv[Nn];
__device__ int   g_deg[Nn];
__device__ int   g_indeg[Nn];
__device__ int   g_rowptr[Nn + 1];
__device__ int   g_cursor[Nn];
__device__ __align__(128) int   g_esrc[Ee];
__device__ __align__(128) float g_ew[Ee];
__device__ __align__(128) float g_ts[5][Nn];          // scalar Chebyshev terms, layer 1
__device__ __align__(128) float g_buf0[FEAT];
__device__ __align__(128) float g_buf1[FEAT];
__device__ __align__(128) float g_buf2[FEAT];
__device__ __align__(128) float g_accb[FEAT];

// ---------------- setup kernels ----------------
__global__ void k_zero() {
    int i = blockIdx.x * blockDim.x + threadIdx.x;
    if (i < Nn) { g_deg[i] = 0; g_indeg[i] = 0; }
}

__global__ void k_hist(const int* __restrict__ src, const int* __restrict__ dst) {
    int e = blockIdx.x * blockDim.x + threadIdx.x;
    if (e < Ee) {
        atomicAdd(&g_deg[src[e]], 1);
        atomicAdd(&g_indeg[dst[e]], 1);
    }
}

__global__ void k_dinv() {
    int i = blockIdx.x * blockDim.x + threadIdx.x;
    if (i < Nn) {
        int d = g_deg[i];
        g_dinv[i] = (d > 0) ? rsqrtf((float)d) : 0.0f;
    }
}

// single-block exclusive scan of g_indeg -> g_rowptr / g_cursor (1024 thr x 64 each)
__global__ void k_scan() {
    __shared__ int part[1024];
    int t = threadIdx.x;
    int base = t * 64;
    int sum = 0;
#pragma unroll 8
    for (int i = 0; i < 64; i++) sum += g_indeg[base + i];
    part[t] = sum;
    __syncthreads();
    for (int off = 1; off < 1024; off <<= 1) {
        int v = 0;
        if (t >= off) v = part[t - off];
        __syncthreads();
        part[t] += v;
        __syncthreads();
    }
    int run = (t == 0) ? 0 : part[t - 1];
    for (int i = 0; i < 64; i++) {
        int c = g_indeg[base + i];
        g_rowptr[base + i] = run;
        g_cursor[base + i] = run;
        run += c;
    }
    if (t == 1023) g_rowptr[Nn] = run;   // == Ee
}

__global__ void k_scatter(const int* __restrict__ src, const int* __restrict__ dst) {
    int e = blockIdx.x * blockDim.x + threadIdx.x;
    if (e < Ee) {
        int s = src[e], d = dst[e];
        int pos = atomicAdd(&g_cursor[d], 1);
        g_esrc[pos] = s;
        g_ew[pos]   = -g_dinv[s] * g_dinv[d];
    }
}

// ---------------- layer 1 (F = 1) ----------------
// tout[n] = alpha * sum_{e in row n} w[e]*tin[src[e]]  -  beta * tprev[n]
__global__ void k_prop_scalar(const float* __restrict__ tin, const float* __restrict__ tprev,
                              float* __restrict__ tout, float alpha, float beta) {
    int warp = threadIdx.x >> 5, lane = threadIdx.x & 31;
    int n = blockIdx.x * (blockDim.x >> 5) + warp;
    int s0 = g_rowptr[n], s1 = g_rowptr[n + 1];
    float acc = 0.0f;
    for (int e = s0 + lane; e < s1; e += 32)
        acc = fmaf(g_ew[e], tin[g_esrc[e]], acc);
#pragma unroll
    for (int off = 16; off > 0; off >>= 1)
        acc += __shfl_xor_sync(0xffffffffu, acc, off);
    if (lane == 0)
        tout[n] = alpha * acc - beta * tprev[n];
}

// h[n][j] = relu(b1[j] + x[n]*W1[0][j] + sum_{k=1..4} ts[k][n]*W1[k][j])
__global__ void k_layer1_out(const float* __restrict__ x, const float* __restrict__ W1,
                             const float* __restrict__ b1, float* __restrict__ h) {
    int warp = threadIdx.x >> 5, lane = threadIdx.x & 31;
    int n = blockIdx.x * (blockDim.x >> 5) + warp;
    float acc = b1[lane] + x[n] * W1[lane];
#pragma unroll
    for (int k = 1; k < 5; k++)
        acc = fmaf(g_ts[k][n], W1[k * HID + lane], acc);
    h[n * HID + lane] = fmaxf(acc, 0.0f);
}

// ---------------- layers 2/3 (F = 32) ----------------
// out[n][:] = T[n][:] @ W    (initializes accumulator for k = 0 term)
__global__ void k_matmul_init(const float* __restrict__ T, const float* __restrict__ W,
                              float* __restrict__ out) {
    __shared__ float Wsh[HID * HID];
    for (int i = threadIdx.x; i < HID * HID; i += blockDim.x) Wsh[i] = W[i];
    __syncthreads();
    int warp = threadIdx.x >> 5, lane = threadIdx.x & 31;
    int n = blockIdx.x * (blockDim.x >> 5) + warp;
    float val = T[n * HID + lane];
    float o = 0.0f;
#pragma unroll
    for (int i = 0; i < HID; i++) {
        float vi = __shfl_sync(0xffffffffu, val, i);
        o = fmaf(vi, Wsh[i * HID + lane], o);
    }
    out[n * HID + lane] = o;
}

// val = alpha*prop(tin)[n][lane] - beta*tprev[n][lane];  tout = val;  out += val @ W
__global__ void k_cheb_step(const float* __restrict__ tin, const float* __restrict__ tprev,
                            float* __restrict__ tout, const float* __restrict__ W,
                            float* __restrict__ outacc, float alpha, float beta) {
    __shared__ float Wsh[HID * HID];
    for (int i = threadIdx.x; i < HID * HID; i += blockDim.x) Wsh[i] = W[i];
    __syncthreads();
    int warp = threadIdx.x >> 5, lane = threadIdx.x & 31;
    int n = blockIdx.x * (blockDim.x >> 5) + warp;
    int s0 = g_rowptr[n], s1 = g_rowptr[n + 1];
    float acc = 0.0f;
    int base = s0;
    // full 32-edge chunks: lane-cooperative edge load, shuffle-broadcast consume
    for (; base + 32 <= s1; base += 32) {
        int   s = g_esrc[base + lane];
        float w = g_ew[base + lane];
#pragma unroll 8
        for (int t = 0; t < 32; t++) {
            int   ss = __shfl_sync(0xffffffffu, s, t);
            float ww = __shfl_sync(0xffffffffu, w, t);
            acc = fmaf(ww, tin[ss * HID + lane], acc);
        }
    }
    if (base < s1) {
        int e = base + lane;
        int s = 0; float w = 0.0f;
        if (e < s1) { s = g_esrc[e]; w = g_ew[e]; }
        int cnt = s1 - base;
        for (int t = 0; t < cnt; t++) {
            int   ss = __shfl_sync(0xffffffffu, s, t);
            float ww = __shfl_sync(0xffffffffu, w, t);
            acc = fmaf(ww, tin[ss * HID + lane], acc);
        }
    }
    float val = alpha * acc - beta * tprev[n * HID + lane];
    tout[n * HID + lane] = val;
    float o = 0.0f;
#pragma unroll
    for (int i = 0; i < HID; i++) {
        float vi = __shfl_sync(0xffffffffu, val, i);
        o = fmaf(vi, Wsh[i * HID + lane], o);
    }
    outacc[n * HID + lane] += o;
}

__global__ void k_bias_act(const float* __restrict__ a, const float* __restrict__ b,
                           float* __restrict__ dst, int relu) {
    int i = blockIdx.x * blockDim.x + threadIdx.x;
    if (i < FEAT) {
        float v = a[i] + b[i & (HID - 1)];
        dst[i] = relu ? fmaxf(v, 0.0f) : v;
    }
}

// ---------------- final linear (8 x 262144) @ (262144 x 33) ----------------
__global__ void k_out_init(float* __restrict__ out, const float* __restrict__ bl) {
    int t = threadIdx.x;
    if (t < GNUM * OSZ) out[t] = bl[t % OSZ];
}

__global__ void k_final(const float* __restrict__ h, const float* __restrict__ Wl,
                        float* __restrict__ out) {
    int t = threadIdx.x;
    if (t >= GNUM * OSZ) return;
    int g = t / OSZ, j = t % OSZ;
    const int CH = (ISZ * HID) / gridDim.x;
    int i0 = blockIdx.x * CH;
    const float* hg = h + g * (ISZ * HID);
    float acc = 0.0f;
#pragma unroll 4
    for (int i = i0; i < i0 + CH; i++)
        acc = fmaf(hg[i], Wl[i * OSZ + j], acc);
    atomicAdd(&out[t], acc);
}

// ---------------- launch ----------------
extern "C" void kernel_launch(void* const* d_in, const int* in_sizes, int n_in,
                              void* d_out, int out_size) {
    const float* x  = (const float*)d_in[0];
    const int*   ei = (const int*)  d_in[1];
    const float* W1 = (const float*)d_in[3];
    const float* b1 = (const float*)d_in[4];
    const float* W2 = (const float*)d_in[5];
    const float* b2 = (const float*)d_in[6];
    const float* W3 = (const float*)d_in[7];
    const float* b3 = (const float*)d_in[8];
    const float* Wl = (const float*)d_in[9];
    const float* bl = (const float*)d_in[10];
    float* out = (float*)d_out;

    const int* src = ei;
    const int* dst = ei + Ee;

    float *buf0, *buf1, *buf2, *acc, *ts;
    cudaGetSymbolAddress((void**)&buf0, g_buf0);
    cudaGetSymbolAddress((void**)&buf1, g_buf1);
    cudaGetSymbolAddress((void**)&buf2, g_buf2);
    cudaGetSymbolAddress((void**)&acc,  g_accb);
    cudaGetSymbolAddress((void**)&ts,   g_ts);

    const int EB = Ee / 256;      // edge-parallel blocks
    const int NB = Nn / 256;      // node-parallel blocks
    const int PB = Nn / 8;        // warp-per-node blocks (256 thr = 8 warps)

    // --- graph preprocessing: degrees, dinv, CSR by dst ---
    k_zero   <<<NB, 256>>>();
    k_hist   <<<EB, 256>>>(src, dst);
    k_dinv   <<<NB, 256>>>();
    k_scan   <<<1, 1024>>>();
    k_scatter<<<EB, 256>>>(src, dst);

    // --- layer 1 (scalar features) ---
    k_prop_scalar<<<PB, 256>>>(x,            x,            ts + 1 * Nn, 1.f, 0.f);
    k_prop_scalar<<<PB, 256>>>(ts + 1 * Nn,  x,            ts + 2 * Nn, 2.f, 1.f);
    k_prop_scalar<<<PB, 256>>>(ts + 2 * Nn,  ts + 1 * Nn,  ts + 3 * Nn, 2.f, 1.f);
    k_prop_scalar<<<PB, 256>>>(ts + 3 * Nn,  ts + 2 * Nn,  ts + 4 * Nn, 2.f, 1.f);
    k_layer1_out <<<PB, 256>>>(x, W1, b1, buf0);          // H1 -> buf0

    // --- layer 2 (X = buf0) ---
    k_matmul_init<<<PB, 256>>>(buf0, W2, acc);
    k_cheb_step  <<<PB, 256>>>(buf0, buf0, buf1, W2 + 1024, acc, 1.f, 0.f); // T1
    k_cheb_step  <<<PB, 256>>>(buf1, buf0, buf2, W2 + 2048, acc, 2.f, 1.f); // T2
    k_cheb_step  <<<PB, 256>>>(buf2, buf1, buf0, W2 + 3072, acc, 2.f, 1.f); // T3
    k_cheb_step  <<<PB, 256>>>(buf0, buf2, buf1, W2 + 4096, acc, 2.f, 1.f); // T4
    k_bias_act   <<<FEAT / 256, 256>>>(acc, b2, buf2, 1);  // H2 -> buf2

    // --- layer 3 (X = buf2) ---
    k_matmul_init<<<PB, 256>>>(buf2, W3, acc);
    k_cheb_step  <<<PB, 256>>>(buf2, buf2, buf0, W3 + 1024, acc, 1.f, 0.f); // T1
    k_cheb_step  <<<PB, 256>>>(buf0, buf2, buf1, W3 + 2048, acc, 2.f, 1.f); // T2
    k_cheb_step  <<<PB, 256>>>(buf1, buf0, buf2, W3 + 3072, acc, 2.f, 1.f); // T3
    k_cheb_step  <<<PB, 256>>>(buf2, buf1, buf0, W3 + 4096, acc, 2.f, 1.f); // T4
    k_bias_act   <<<FEAT / 256, 256>>>(acc, b3, buf1, 0);  // H3 -> buf1

    // --- final linear ---
    k_out_init<<<1, 264>>>(out, bl);
    k_final   <<<512, 264>>>(buf1, Wl, out);
}

// round 2
// speedup vs baseline: 1.3916x; 1.3916x over previous
#include <cuda_runtime.h>

// ---------------- problem constants (fixed shapes) ----------------
#define Nn   65536          // total nodes
#define Ee   2097152        // edges
#define HID  32
#define GNUM 8
#define ISZ  8192
#define OSZ  33
#define FEAT (Nn * HID)

// ---------------- static device scratch ----------------
__device__ __align__(128) float g_dinv[Nn];
__device__ int   g_deg[Nn];
__device__ int   g_indeg[Nn];
__device__ int   g_bsum[256];
__device__ int   g_boff[256];
__device__ __align__(128) int   g_rowptr[Nn + 1];
__device__ int   g_cursor[Nn];
__device__ __align__(128) int   g_esrc[Ee];
__device__ __align__(128) float g_ew[Ee];
__device__ __align__(128) float g_ts[5][Nn];          // scalar Chebyshev terms, layer 1
__device__ __align__(128) float g_buf0[FEAT];
__device__ __align__(128) float g_buf1[FEAT];
__device__ __align__(128) float g_buf2[FEAT];
__device__ __align__(128) float g_accb[FEAT];

// ---------------- setup kernels ----------------
__global__ void k_zero() {
    int i = blockIdx.x * blockDim.x + threadIdx.x;
    if (i < Nn) { g_deg[i] = 0; g_indeg[i] = 0; }
}

__global__ void k_hist(const int* __restrict__ src, const int* __restrict__ dst) {
    int e = blockIdx.x * blockDim.x + threadIdx.x;
    if (e < Ee) {
        atomicAdd(&g_deg[src[e]], 1);
        atomicAdd(&g_indeg[dst[e]], 1);
    }
}

__global__ void k_dinv() {
    int i = blockIdx.x * blockDim.x + threadIdx.x;
    if (i < Nn) {
        int d = g_deg[i];
        g_dinv[i] = (d > 0) ? rsqrtf((float)d) : 0.0f;
    }
}

// ---- 3-stage parallel exclusive scan of g_indeg -> g_rowptr / g_cursor ----
__global__ void k_bsum() {               // 256 blocks x 256 threads
    __shared__ int sh[256];
    int t = threadIdx.x;
    sh[t] = g_indeg[blockIdx.x * 256 + t];
    __syncthreads();
    for (int off = 128; off > 0; off >>= 1) {
        if (t < off) sh[t] += sh[t + off];
        __syncthreads();
    }
    if (t == 0) g_bsum[blockIdx.x] = sh[0];
}

__global__ void k_bscan() {              // 1 block x 256 threads
    __shared__ int sh[256];
    int t = threadIdx.x;
    sh[t] = g_bsum[t];
    __syncthreads();
    for (int off = 1; off < 256; off <<= 1) {
        int v = (t >= off) ? sh[t - off] : 0;
        __syncthreads();
        sh[t] += v;
        __syncthreads();
    }
    g_boff[t] = (t == 0) ? 0 : sh[t - 1];
}

__global__ void k_rowptr() {             // 256 blocks x 256 threads
    __shared__ int sh[256];
    int t = threadIdx.x;
    int i = blockIdx.x * 256 + t;
    int v = g_indeg[i];
    sh[t] = v;
    __syncthreads();
    for (int off = 1; off < 256; off <<= 1) {
        int u = (t >= off) ? sh[t - off] : 0;
        __syncthreads();
        sh[t] += u;
        __syncthreads();
    }
    int excl = sh[t] - v + g_boff[blockIdx.x];
    g_rowptr[i] = excl;
    g_cursor[i] = excl;
    if (i == 0) g_rowptr[Nn] = Ee;
}

__global__ void k_scatter(const int* __restrict__ src, const int* __restrict__ dst) {
    int e = blockIdx.x * blockDim.x + threadIdx.x;
    if (e < Ee) {
        int s = src[e], d = dst[e];
        int pos = atomicAdd(&g_cursor[d], 1);
        g_esrc[pos] = s;
        g_ew[pos]   = -g_dinv[s] * g_dinv[d];
    }
}

// ---------------- layer 1 (F = 1) ----------------
__global__ void k_prop_scalar(const float* __restrict__ tin, const float* __restrict__ tprev,
                              float* __restrict__ tout, float alpha, float beta) {
    int warp = threadIdx.x >> 5, lane = threadIdx.x & 31;
    int n = blockIdx.x * (blockDim.x >> 5) + warp;
    int s0 = g_rowptr[n], s1 = g_rowptr[n + 1];
    float acc = 0.0f;
    for (int e = s0 + lane; e < s1; e += 32)
        acc = fmaf(g_ew[e], tin[g_esrc[e]], acc);
#pragma unroll
    for (int off = 16; off > 0; off >>= 1)
        acc += __shfl_xor_sync(0xffffffffu, acc, off);
    if (lane == 0)
        tout[n] = alpha * acc - beta * tprev[n];
}

__global__ void k_layer1_out(const float* __restrict__ x, const float* __restrict__ W1,
                             const float* __restrict__ b1, float* __restrict__ h) {
    int warp = threadIdx.x >> 5, lane = threadIdx.x & 31;
    int n = blockIdx.x * (blockDim.x >> 5) + warp;
    float acc = b1[lane] + x[n] * W1[lane];
#pragma unroll
    for (int k = 1; k < 5; k++)
        acc = fmaf(g_ts[k][n], W1[k * HID + lane], acc);
    h[n * HID + lane] = fmaxf(acc, 0.0f);
}

// ---------------- layers 2/3 (F = 32) ----------------
// float4-vectorized sparse prop: warp-per-node, lane = (edge-subgroup, feature-quarter).
// Returns the propagated value for feature = lane of node n (scalar-per-lane layout).
__device__ __forceinline__ float cheb_prop(const float4* __restrict__ tin4, int n, int lane) {
    int sub = lane >> 3, q = lane & 7;
    int sb = sub << 3;
    int s0 = g_rowptr[n], s1 = g_rowptr[n + 1];
    float4 a = make_float4(0.f, 0.f, 0.f, 0.f);
    for (int base = s0; base < s1; base += 32) {
        int e = base + lane;
        int s = 0; float w = 0.f;
        if (e < s1) { s = g_esrc[e]; w = g_ew[e]; }
#pragma unroll
        for (int t = 0; t < 8; t++) {
            int   ss = __shfl_sync(0xffffffffu, s, sb + t);
            float ww = __shfl_sync(0xffffffffu, w, sb + t);
            float4 r = __ldg(&tin4[ss * 8 + q]);
            a.x = fmaf(ww, r.x, a.x);
            a.y = fmaf(ww, r.y, a.y);
            a.z = fmaf(ww, r.z, a.z);
            a.w = fmaf(ww, r.w, a.w);
        }
    }
    // reduce across the 4 edge-subgroups (lanes q, q+8, q+16, q+24)
#pragma unroll
    for (int off = 8; off <= 16; off <<= 1) {
        a.x += __shfl_xor_sync(0xffffffffu, a.x, off);
        a.y += __shfl_xor_sync(0xffffffffu, a.y, off);
        a.z += __shfl_xor_sync(0xffffffffu, a.z, off);
        a.w += __shfl_xor_sync(0xffffffffu, a.w, off);
    }
    // redistribute: lane owns scalar feature = lane
    int sl = lane >> 2;
    float vx = __shfl_sync(0xffffffffu, a.x, sl);
    float vy = __shfl_sync(0xffffffffu, a.y, sl);
    float vz = __shfl_sync(0xffffffffu, a.z, sl);
    float vw = __shfl_sync(0xffffffffu, a.w, sl);
    int c = lane & 3;
    return c == 0 ? vx : c == 1 ? vy : c == 2 ? vz : vw;
}

__device__ __forceinline__ float mm32(float val, const float* __restrict__ Wsh, int lane) {
    float o = 0.f;
#pragma unroll
    for (int i = 0; i < HID; i++)
        o = fmaf(__shfl_sync(0xffffffffu, val, i), Wsh[i * HID + lane], o);
    return o;
}

// First step: T0 = tin, T1 = prop(T0). outacc = T0@W0 + T1@W1; tout = T1.
__global__ void k_cheb_first(const float* __restrict__ tin, float* __restrict__ tout,
                             const float* __restrict__ W01, float* __restrict__ outacc) {
    __shared__ float Wsh[2 * HID * HID];
    for (int i = threadIdx.x; i < 2 * HID * HID; i += blockDim.x) Wsh[i] = W01[i];
    __syncthreads();
    int warp = threadIdx.x >> 5, lane = threadIdx.x & 31;
    int n = blockIdx.x * (blockDim.x >> 5) + warp;
    float val1 = cheb_prop((const float4*)tin, n, lane);
    float val0 = tin[n * HID + lane];
    tout[n * HID + lane] = val1;
    float o = mm32(val0, Wsh, lane) + mm32(val1, Wsh + HID * HID, lane);
    outacc[n * HID + lane] = o;
}

// Middle step: Tk = 2*prop(T_{k-1}) - T_{k-2}. outacc += Tk@Wk; tout = Tk.
__global__ void k_cheb_mid(const float* __restrict__ tin, const float* __restrict__ tprev,
                           float* __restrict__ tout, const float* __restrict__ W,
                           float* __restrict__ outacc) {
    __shared__ float Wsh[HID * HID];
    for (int i = threadIdx.x; i < HID * HID; i += blockDim.x) Wsh[i] = W[i];
    __syncthreads();
    int warp = threadIdx.x >> 5, lane = threadIdx.x & 31;
    int n = blockIdx.x * (blockDim.x >> 5) + warp;
    float p = cheb_prop((const float4*)tin, n, lane);
    float val = 2.0f * p - tprev[n * HID + lane];
    tout[n * HID + lane] = val;
    outacc[n * HID + lane] += mm32(val, Wsh, lane);
}

// Last step: Tk = 2*prop(T_{k-1}) - T_{k-2}. H = act(outacc + Tk@Wk + bias).
__global__ void k_cheb_last(const float* __restrict__ tin, const float* __restrict__ tprev,
                            const float* __restrict__ W, const float* __restrict__ outacc,
                            const float* __restrict__ bias, int relu,
                            float* __restrict__ hout) {
    __shared__ float Wsh[HID * HID];
    for (int i = threadIdx.x; i < HID * HID; i += blockDim.x) Wsh[i] = W[i];
    __syncthreads();
    int warp = threadIdx.x >> 5, lane = threadIdx.x & 31;
    int n = blockIdx.x * (blockDim.x >> 5) + warp;
    float p = cheb_prop((const float4*)tin, n, lane);
    float val = 2.0f * p - tprev[n * HID + lane];
    float o = outacc[n * HID + lane] + mm32(val, Wsh, lane) + bias[lane];
    hout[n * HID + lane] = relu ? fmaxf(o, 0.0f) : o;
}

// ---------------- final linear (8 x 262144) @ (262144 x 33) ----------------
__global__ void k_out_init(float* __restrict__ out, const float* __restrict__ bl) {
    int t = threadIdx.x;
    if (t < GNUM * OSZ) out[t] = bl[t % OSZ];
}

__global__ void k_final(const float* __restrict__ h, const float* __restrict__ Wl,
                        float* __restrict__ out) {
    int t = threadIdx.x;
    if (t >= GNUM * OSZ) return;
    int g = t / OSZ, j = t % OSZ;
    const int CH = (ISZ * HID) / gridDim.x;
    int i0 = blockIdx.x * CH;
    const float* hg = h + g * (ISZ * HID);
    float acc = 0.0f;
#pragma unroll 4
    for (int i = i0; i < i0 + CH; i++)
        acc = fmaf(hg[i], Wl[i * OSZ + j], acc);
    atomicAdd(&out[t], acc);
}

// ---------------- launch ----------------
extern "C" void kernel_launch(void* const* d_in, const int* in_sizes, int n_in,
                              void* d_out, int out_size) {
    const float* x  = (const float*)d_in[0];
    const int*   ei = (const int*)  d_in[1];
    const float* W1 = (const float*)d_in[3];
    const float* b1 = (const float*)d_in[4];
    const float* W2 = (const float*)d_in[5];
    const float* b2 = (const float*)d_in[6];
    const float* W3 = (const float*)d_in[7];
    const float* b3 = (const float*)d_in[8];
    const float* Wl = (const float*)d_in[9];
    const float* bl = (const float*)d_in[10];
    float* out = (float*)d_out;

    const int* src = ei;
    const int* dst = ei + Ee;

    float *buf0, *buf1, *buf2, *acc, *ts;
    cudaGetSymbolAddress((void**)&buf0, g_buf0);
    cudaGetSymbolAddress((void**)&buf1, g_buf1);
    cudaGetSymbolAddress((void**)&buf2, g_buf2);
    cudaGetSymbolAddress((void**)&acc,  g_accb);
    cudaGetSymbolAddress((void**)&ts,   g_ts);

    const int EB = Ee / 256;      // edge-parallel blocks
    const int NB = Nn / 256;      // node-parallel blocks
    const int PB = Nn / 8;        // warp-per-node blocks (256 thr = 8 warps)

    // --- graph preprocessing: degrees, dinv, CSR by dst ---
    k_zero   <<<NB, 256>>>();
    k_hist   <<<EB, 256>>>(src, dst);
    k_dinv   <<<NB, 256>>>();
    k_bsum   <<<256, 256>>>();
    k_bscan  <<<1, 256>>>();
    k_rowptr <<<256, 256>>>();
    k_scatter<<<EB, 256>>>(src, dst);

    // --- layer 1 (scalar features) ---
    k_prop_scalar<<<PB, 256>>>(x,            x,            ts + 1 * Nn, 1.f, 0.f);
    k_prop_scalar<<<PB, 256>>>(ts + 1 * Nn,  x,            ts + 2 * Nn, 2.f, 1.f);
    k_prop_scalar<<<PB, 256>>>(ts + 2 * Nn,  ts + 1 * Nn,  ts + 3 * Nn, 2.f, 1.f);
    k_prop_scalar<<<PB, 256>>>(ts + 3 * Nn,  ts + 2 * Nn,  ts + 4 * Nn, 2.f, 1.f);
    k_layer1_out <<<PB, 256>>>(x, W1, b1, buf0);          // H1 -> buf0

    // --- layer 2 (T0 = buf0 = H1) ---
    k_cheb_first<<<PB, 256>>>(buf0, buf1, W2, acc);                      // T1 -> buf1
    k_cheb_mid  <<<PB, 256>>>(buf1, buf0, buf2, W2 + 2048, acc);         // T2 -> buf2
    k_cheb_mid  <<<PB, 256>>>(buf2, buf1, buf0, W2 + 3072, acc);         // T3 -> buf0
    k_cheb_last <<<PB, 256>>>(buf0, buf2, W2 + 4096, acc, b2, 1, buf1);  // H2 -> buf1

    // --- layer 3 (T0 = buf1 = H2) ---
    k_cheb_first<<<PB, 256>>>(buf1, buf0, W3, acc);                      // T1 -> buf0
    k_cheb_mid  <<<PB, 256>>>(buf0, buf1, buf2, W3 + 2048, acc);         // T2 -> buf2
    k_cheb_mid  <<<PB, 256>>>(buf2, buf0, buf1, W3 + 3072, acc);         // T3 -> buf1
    k_cheb_last <<<PB, 256>>>(buf1, buf2, W3 + 4096, acc, b3, 0, buf0);  // H3 -> buf0

    // --- final linear ---
    k_out_init<<<1, 264>>>(out, bl);
    k_final   <<<512, 264>>>(buf0, Wl, out);
}

// round 3
// speedup vs baseline: 1.7431x; 1.2525x over previous
#include <cuda_runtime.h>

// ---------------- problem constants (fixed shapes) ----------------
#define Nn   65536          // total nodes
#define Ee   2097152        // edges
#define HID  32
#define GNUM 8
#define ISZ  8192
#define OSZ  33
#define FEAT (Nn * HID)

// ---------------- static device scratch ----------------
__device__ __align__(128) float g_dinv[Nn];
__device__ __align__(128) int   g_deg[Nn];
__device__ __align__(128) int   g_indeg[Nn];
__device__ int   g_bsum[256];
__device__ int   g_boff[256];
__device__ __align__(128) int   g_rowptr[Nn + 1];
__device__ int   g_cursor[Nn];
__device__ __align__(128) int2  g_epack[Ee];          // (src, weight bits)
__device__ __align__(128) float g_ts[5][Nn];          // scalar Chebyshev terms, layer 1
__device__ __align__(128) float g_buf0[FEAT];
__device__ __align__(128) float g_buf1[FEAT];
__device__ __align__(128) float g_buf2[FEAT];
__device__ __align__(128) float g_accb[FEAT];

// ---------------- setup kernels ----------------
__global__ void k_hist(const int* __restrict__ src, const int* __restrict__ dst) {
    int e = blockIdx.x * blockDim.x + threadIdx.x;
    if (e < Ee) {
        atomicAdd(&g_deg[src[e]], 1);
        atomicAdd(&g_indeg[dst[e]], 1);
    }
}

__global__ void k_dinv() {
    int i = blockIdx.x * blockDim.x + threadIdx.x;
    if (i < Nn) {
        int d = g_deg[i];
        g_dinv[i] = (d > 0) ? rsqrtf((float)d) : 0.0f;
    }
}

// ---- 3-stage parallel exclusive scan of g_indeg -> g_rowptr / g_cursor ----
__global__ void k_bsum() {               // 256 blocks x 256 threads
    __shared__ int sh[256];
    int t = threadIdx.x;
    sh[t] = g_indeg[blockIdx.x * 256 + t];
    __syncthreads();
    for (int off = 128; off > 0; off >>= 1) {
        if (t < off) sh[t] += sh[t + off];
        __syncthreads();
    }
    if (t == 0) g_bsum[blockIdx.x] = sh[0];
}

__global__ void k_bscan() {              // 1 block x 256 threads
    __shared__ int sh[256];
    int t = threadIdx.x;
    sh[t] = g_bsum[t];
    __syncthreads();
    for (int off = 1; off < 256; off <<= 1) {
        int v = (t >= off) ? sh[t - off] : 0;
        __syncthreads();
        sh[t] += v;
        __syncthreads();
    }
    g_boff[t] = (t == 0) ? 0 : sh[t - 1];
}

__global__ void k_rowptr() {             // 256 blocks x 256 threads
    __shared__ int sh[256];
    int t = threadIdx.x;
    int i = blockIdx.x * 256 + t;
    int v = g_indeg[i];
    sh[t] = v;
    __syncthreads();
    for (int off = 1; off < 256; off <<= 1) {
        int u = (t >= off) ? sh[t - off] : 0;
        __syncthreads();
        sh[t] += u;
        __syncthreads();
    }
    int excl = sh[t] - v + g_boff[blockIdx.x];
    g_rowptr[i] = excl;
    g_cursor[i] = excl;
    if (i == 0) g_rowptr[Nn] = Ee;
}

__global__ void k_scatter(const int* __restrict__ src, const int* __restrict__ dst) {
    int e = blockIdx.x * blockDim.x + threadIdx.x;
    if (e < Ee) {
        int s = src[e], d = dst[e];
        int pos = atomicAdd(&g_cursor[d], 1);
        float w = -g_dinv[s] * g_dinv[d];
        g_epack[pos] = make_int2(s, __float_as_int(w));
    }
}

// ---------------- layer 1 (F = 1) ----------------
__global__ void k_prop_scalar(const float* __restrict__ tin, const float* __restrict__ tprev,
                              float* __restrict__ tout, float alpha, float beta) {
    int warp = threadIdx.x >> 5, lane = threadIdx.x & 31;
    int n = blockIdx.x * (blockDim.x >> 5) + warp;
    int s0 = g_rowptr[n], s1 = g_rowptr[n + 1];
    float acc = 0.0f;
    for (int e = s0 + lane; e < s1; e += 32) {
        int2 p = g_epack[e];
        acc = fmaf(__int_as_float(p.y), __ldg(&tin[p.x]), acc);
    }
#pragma unroll
    for (int off = 16; off > 0; off >>= 1)
        acc += __shfl_xor_sync(0xffffffffu, acc, off);
    if (lane == 0)
        tout[n] = alpha * acc - beta * tprev[n];
}

__global__ void k_layer1_out(const float* __restrict__ x, const float* __restrict__ W1,
                             const float* __restrict__ b1, float* __restrict__ h) {
    int warp = threadIdx.x >> 5, lane = threadIdx.x & 31;
    int n = blockIdx.x * (blockDim.x >> 5) + warp;
    float acc = b1[lane] + x[n] * W1[lane];
#pragma unroll
    for (int k = 1; k < 5; k++)
        acc = fmaf(g_ts[k][n], W1[k * HID + lane], acc);
    h[n * HID + lane] = fmaxf(acc, 0.0f);
}

// ---------------- layers 2/3 (F = 32) ----------------
// warp = 4 nodes, 8-lane group per node; lane = (g, q), q = feature-quarter.
// Group g accumulates node n's full row as one float4 per lane. No shuffles in
// the edge loop: edge data comes via 8-lane-broadcast LDG.64 (L1-resident,
// sequential walk), gather is one coalesced 128B line per group per edge.
__device__ __forceinline__ float4 cheb_prop4(const float4* __restrict__ tin4, int n, int q) {
    int s0 = __ldg(&g_rowptr[n]), s1 = __ldg(&g_rowptr[n + 1]);
    float4 a = make_float4(0.f, 0.f, 0.f, 0.f);
#pragma unroll 4
    for (int e = s0; e < s1; e++) {
        int2 p = __ldg(&g_epack[e]);
        float w = __int_as_float(p.y);
        float4 r = __ldg(&tin4[p.x * 8 + q]);
        a.x = fmaf(w, r.x, a.x);
        a.y = fmaf(w, r.y, a.y);
        a.z = fmaf(w, r.z, a.z);
        a.w = fmaf(w, r.w, a.w);
    }
    return a;
}

// o += val @ W within an 8-lane group: lane q holds features 4q..4q+3 of val/o.
__device__ __forceinline__ void mm32g(float4& o, float4 val, const float* __restrict__ Wsh,
                                      int lane, int q) {
    int gbase = lane & 24;
#pragma unroll
    for (int i = 0; i < HID; i++) {
        float comp = (i & 3) == 0 ? val.x : (i & 3) == 1 ? val.y : (i & 3) == 2 ? val.z : val.w;
        float vi = __shfl_sync(0xffffffffu, comp, gbase + (i >> 2));
        float4 wv = ((const float4*)Wsh)[i * 8 + q];
        o.x = fmaf(vi, wv.x, o.x);
        o.y = fmaf(vi, wv.y, o.y);
        o.z = fmaf(vi, wv.z, o.z);
        o.w = fmaf(vi, wv.w, o.w);
    }
}

// First step: T0 = tin, T1 = prop(T0). outacc = T0@W0 + T1@W1; tout = T1.
__global__ void k_cheb_first(const float* __restrict__ tin, float* __restrict__ tout,
                             const float* __restrict__ W01, float* __restrict__ outacc) {
    __shared__ float Wsh[2 * HID * HID];
    for (int i = threadIdx.x; i < 2 * HID * HID; i += blockDim.x) Wsh[i] = W01[i];
    __syncthreads();
    int warp = threadIdx.x >> 5, lane = threadIdx.x & 31;
    int g = lane >> 3, q = lane & 7;
    int n = (blockIdx.x * (blockDim.x >> 5) + warp) * 4 + g;
    float4 t1 = cheb_prop4((const float4*)tin, n, q);
    float4 t0 = ((const float4*)tin)[n * 8 + q];
    ((float4*)tout)[n * 8 + q] = t1;
    float4 o = make_float4(0.f, 0.f, 0.f, 0.f);
    mm32g(o, t0, Wsh, lane, q);
    mm32g(o, t1, Wsh + HID * HID, lane, q);
    ((float4*)outacc)[n * 8 + q] = o;
}

// Middle step: Tk = 2*prop(T_{k-1}) - T_{k-2}. outacc += Tk@Wk; tout = Tk.
__global__ void k_cheb_mid(const float* __restrict__ tin, const float* __restrict__ tprev,
                           float* __restrict__ tout, const float* __restrict__ W,
                           float* __restrict__ outacc) {
    __shared__ float Wsh[HID * HID];
    for (int i = threadIdx.x; i < HID * HID; i += blockDim.x) Wsh[i] = W[i];
    __syncthreads();
    int warp = threadIdx.x >> 5, lane = threadIdx.x & 31;
    int g = lane >> 3, q = lane & 7;
    int n = (blockIdx.x * (blockDim.x >> 5) + warp) * 4 + g;
    float4 p = cheb_prop4((const float4*)tin, n, q);
    float4 tp = ((const float4*)tprev)[n * 8 + q];
    float4 val = make_float4(2.f * p.x - tp.x, 2.f * p.y - tp.y,
                             2.f * p.z - tp.z, 2.f * p.w - tp.w);
    ((float4*)tout)[n * 8 + q] = val;
    float4 o = ((const float4*)outacc)[n * 8 + q];
    mm32g(o, val, Wsh, lane, q);
    ((float4*)outacc)[n * 8 + q] = o;
}

// Last step: Tk = 2*prop(T_{k-1}) - T_{k-2}. H = act(outacc + Tk@Wk + bias).
__global__ void k_cheb_last(const float* __restrict__ tin, const float* __restrict__ tprev,
                            const float* __restrict__ W, const float* __restrict__ outacc,
                            const float* __restrict__ bias, int relu,
                            float* __restrict__ hout) {
    __shared__ float Wsh[HID * HID];
    for (int i = threadIdx.x; i < HID * HID; i += blockDim.x) Wsh[i] = W[i];
    __syncthreads();
    int warp = threadIdx.x >> 5, lane = threadIdx.x & 31;
    int g = lane >> 3, q = lane & 7;
    int n = (blockIdx.x * (blockDim.x >> 5) + warp) * 4 + g;
    float4 p = cheb_prop4((const float4*)tin, n, q);
    float4 tp = ((const float4*)tprev)[n * 8 + q];
    float4 val = make_float4(2.f * p.x - tp.x, 2.f * p.y - tp.y,
                             2.f * p.z - tp.z, 2.f * p.w - tp.w);
    float4 o = ((const float4*)outacc)[n * 8 + q];
    mm32g(o, val, Wsh, lane, q);
    float4 bv = ((const float4*)bias)[q];
    o.x += bv.x; o.y += bv.y; o.z += bv.z; o.w += bv.w;
    if (relu) {
        o.x = fmaxf(o.x, 0.f); o.y = fmaxf(o.y, 0.f);
        o.z = fmaxf(o.z, 0.f); o.w = fmaxf(o.w, 0.f);
    }
    ((float4*)hout)[n * 8 + q] = o;
}

// ---------------- final linear (8 x 262144) @ (262144 x 33) ----------------
__global__ void k_out_init(float* __restrict__ out, const float* __restrict__ bl) {
    int t = threadIdx.x;
    if (t < GNUM * OSZ) out[t] = bl[t % OSZ];
}

__global__ void k_final(const float* __restrict__ h, const float* __restrict__ Wl,
                        float* __restrict__ out) {
    int t = threadIdx.x;
    if (t >= GNUM * OSZ) return;
    int g = t / OSZ, j = t % OSZ;
    const int CH = (ISZ * HID) / gridDim.x;
    int i0 = blockIdx.x * CH;
    const float* hg = h + g * (ISZ * HID);
    float acc = 0.0f;
#pragma unroll 4
    for (int i = i0; i < i0 + CH; i++)
        acc = fmaf(__ldg(&hg[i]), __ldg(&Wl[i * OSZ + j]), acc);
    atomicAdd(&out[t], acc);
}

// ---------------- launch ----------------
extern "C" void kernel_launch(void* const* d_in, const int* in_sizes, int n_in,
                              void* d_out, int out_size) {
    const float* x  = (const float*)d_in[0];
    const int*   ei = (const int*)  d_in[1];
    const float* W1 = (const float*)d_in[3];
    const float* b1 = (const float*)d_in[4];
    const float* W2 = (const float*)d_in[5];
    const float* b2 = (const float*)d_in[6];
    const float* W3 = (const float*)d_in[7];
    const float* b3 = (const float*)d_in[8];
    const float* Wl = (const float*)d_in[9];
    const float* bl = (const float*)d_in[10];
    float* out = (float*)d_out;

    const int* src = ei;
    const int* dst = ei + Ee;

    float *buf0, *buf1, *buf2, *acc, *ts;
    void *degp, *indegp;
    cudaGetSymbolAddress((void**)&buf0, g_buf0);
    cudaGetSymbolAddress((void**)&buf1, g_buf1);
    cudaGetSymbolAddress((void**)&buf2, g_buf2);
    cudaGetSymbolAddress((void**)&acc,  g_accb);
    cudaGetSymbolAddress((void**)&ts,   g_ts);
    cudaGetSymbolAddress(&degp,   g_deg);
    cudaGetSymbolAddress(&indegp, g_indeg);

    const int EB = Ee / 256;      // edge-parallel blocks
    const int NB = Nn / 256;      // node-parallel blocks
    const int PB = Nn / 8;        // warp-per-node blocks (layer-1 kernels)
    const int QB = Nn / 32;       // 4-nodes-per-warp blocks (heavy props)

    // --- graph preprocessing: degrees, dinv, CSR by dst ---
    cudaMemsetAsync(degp,   0, Nn * sizeof(int));
    cudaMemsetAsync(indegp, 0, Nn * sizeof(int));
    k_hist   <<<EB, 256>>>(src, dst);
    k_dinv   <<<NB, 256>>>();
    k_bsum   <<<256, 256>>>();
    k_bscan  <<<1, 256>>>();
    k_rowptr <<<256, 256>>>();
    k_scatter<<<EB, 256>>>(src, dst);

    // --- layer 1 (scalar features) ---
    k_prop_scalar<<<PB, 256>>>(x,            x,            ts + 1 * Nn, 1.f, 0.f);
    k_prop_scalar<<<PB, 256>>>(ts + 1 * Nn,  x,            ts + 2 * Nn, 2.f, 1.f);
    k_prop_scalar<<<PB, 256>>>(ts + 2 * Nn,  ts + 1 * Nn,  ts + 3 * Nn, 2.f, 1.f);
    k_prop_scalar<<<PB, 256>>>(ts + 3 * Nn,  ts + 2 * Nn,  ts + 4 * Nn, 2.f, 1.f);
    k_layer1_out <<<PB, 256>>>(x, W1, b1, buf0);          // H1 -> buf0

    // --- layer 2 (T0 = buf0 = H1) ---
    k_cheb_first<<<QB, 256>>>(buf0, buf1, W2, acc);                      // T1 -> buf1
    k_cheb_mid  <<<QB, 256>>>(buf1, buf0, buf2, W2 + 2048, acc);         // T2 -> buf2
    k_cheb_mid  <<<QB, 256>>>(buf2, buf1, buf0, W2 + 3072, acc);         // T3 -> buf0
    k_cheb_last <<<QB, 256>>>(buf0, buf2, W2 + 4096, acc, b2, 1, buf1);  // H2 -> buf1

    // --- layer 3 (T0 = buf1 = H2) ---
    k_cheb_first<<<QB, 256>>>(buf1, buf0, W3, acc);                      // T1 -> buf0
    k_cheb_mid  <<<QB, 256>>>(buf0, buf1, buf2, W3 + 2048, acc);         // T2 -> buf2
    k_cheb_mid  <<<QB, 256>>>(buf2, buf0, buf1, W3 + 3072, acc);         // T3 -> buf1
    k_cheb_last <<<QB, 256>>>(buf1, buf2, W3 + 4096, acc, b3, 0, buf0);  // H3 -> buf0

    // --- final linear ---
    k_out_init<<<1, 264>>>(out, bl);
    k_final   <<<512, 264>>>(buf0, Wl, out);
}